// round 15
// baseline (speedup 1.0000x reference)
#include <cuda_runtime.h>
#include <math.h>

#define NN 1024
#define NH 64
#define NC 8              // Taylor terms (degree 7)
#define NCP 9             // padded stride (odd -> conflict-free)
#define SCALE 0.125f
#define KMAX 20
#define NB 128
#define NT 512
#define RPB 8
#define GATE_THR (-2.1972245773362196f)   // logit(0.1)

// -------- device scratch --------
__device__ float g_q[NH][NN], g_k[NH][NN], g_v[NH][NN];
__device__ float g_gk[NH][NN], g_gv[NH][NN];
__device__ __align__(16) float g_xpart[NB][64];   // colsum * hg_w (flat-summable)
__device__ __align__(16) float g_entpart[NB];
__device__ float g_hdD[NH][NC], g_hdDg[NH][NC], g_hdSv[NH][NC];
__device__ float g_cLp[NH][NC], g_cLn[NH][NC];   // local-numerator coefs (km==KMAX)
__device__ __align__(16) float g_tkT[KMAX][NH];  // slow path (km != KMAX)
__device__ __align__(16) float g_tvT[KMAX][NH];
__device__ __align__(16) float g_bkT[KMAX][NH];
__device__ __align__(16) float g_bvT[KMAX][NH];
__device__ float g_vpreT[KMAX][NH];
__device__ unsigned g_barcnt2[2][8][64];   // [bar][group][pad]; 256B apart; monotonic

__constant__ float c_invf[NC] = {
    1.0f, 1.0f, 0.5f, 1.66666672e-01f, 4.16666679e-02f, 8.33333377e-03f,
    1.38888892e-03f, 1.98412701e-04f };

__device__ __forceinline__ unsigned ford(float f) {
    unsigned u = __float_as_uint(f);
    return (u & 0x80000000u) ? ~u : (u | 0x80000000u);
}

__device__ __forceinline__ float horner8(const float* c, float a) {
    float r = c[NC - 1];
#pragma unroll
    for (int j = NC - 2; j >= 0; --j) r = fmaf(r, a, c[j]);
    return r;
}

// distributed grid barrier: 8 padded counters, release-add + acquire-poll sum
__device__ __forceinline__ void gridbar(int idx, int grp) {
    __syncthreads();
    if (threadIdx.x == 0) {
        unsigned* cnt = &g_barcnt2[idx][grp][0];
        unsigned my;
        asm volatile("atom.release.gpu.global.add.u32 %0, [%1], 1;"
                     : "=r"(my) : "l"(cnt) : "memory");
        const unsigned target = (my / 16u + 1u) * 128u;
        unsigned sum;
        do {
            sum = 0;
#pragma unroll
            for (int j = 0; j < 8; ++j) {
                unsigned v;
                asm volatile("ld.acquire.gpu.global.u32 %0, [%1];"
                             : "=r"(v) : "l"(&g_barcnt2[idx][j][0]) : "memory");
                sum += v;
            }
        } while (sum < target);
    }
    __syncthreads();
}

__global__ __launch_bounds__(NT, 1)
void fused_kernel(const float* __restrict__ x,
                  const float* __restrict__ qkv_w,  const float* __restrict__ qkv_b,
                  const float* __restrict__ gqkv_w, const float* __restrict__ gqkv_b,
                  const float* __restrict__ cg_w,   const float* __restrict__ cg_b,
                  const float* __restrict__ hg_w,   const float* __restrict__ hg_b,
                  const float* __restrict__ fus_w,  const float* __restrict__ fus_b,
                  const float* __restrict__ proj_w, const float* __restrict__ proj_b,
                  float* __restrict__ out) {
    extern __shared__ __align__(16) float dynS[];   // [8192] fus_w, [4096] proj_w
    float* fusW  = dynS;
    float* projW = dynS + 8192;

    __shared__ __align__(16) float xs[512], xmS[512], qsS[512], gqS[512]; // persist A->C
    __shared__ __align__(16) float kk[NN], vv[NN];
    __shared__ __align__(16) float qs[512];
    __shared__ __align__(16) float cDs[64 * NCP], cDgS[64 * NCP], cSvS[64 * NCP];
    __shared__ __align__(16) float cLp[64 * NCP], cLn[64 * NCP];
    __shared__ __align__(16) float lxS[512], gxS[512], ttS[512];
    __shared__ unsigned long long candS[160];
    __shared__ float red[17][16];
    __shared__ float Rall[17];
    __shared__ float coefD[NC], coefS1[NC];
    __shared__ float selK[KMAX], selV[KMAX];
    __shared__ float impred[16];
    __shared__ int   km_s, early_s;

    const int b = blockIdx.x;
    const int t = threadIdx.x;
    const int lane = t & 31, wid = t >> 5;
    const int n0 = b * RPB;

    // ================= Phase A: gate + qkv/gqkv GEMMs (8 rows) =================
    xs[t] = x[n0 * 64 + t];            // RPB*64 == NT

    // prefetch qkv/gqkv j4==0 weight group (independent of x / gate)
    float2 pwA, pwB, pwC, pwD;
    const bool isg = (t >= 96) && (t < 192);
    const int qc = (t < 192) ? ((isg ? (t - 96) : t) * 2) : 0;
    const float* wp = isg ? gqkv_w : qkv_w;
    if (t < 192) {
        pwA = *(const float2*)(wp + 0 * 192 + qc);
        pwB = *(const float2*)(wp + 1 * 192 + qc);
        pwC = *(const float2*)(wp + 2 * 192 + qc);
        pwD = *(const float2*)(wp + 3 * 192 + qc);
    }
    __syncthreads();

    if (t < 64) {   // column sum pre-scaled by hg_w (flat-summable later)
        float s = 0.f;
#pragma unroll
        for (int r = 0; r < RPB; ++r) s += xs[r * 64 + t];
        g_xpart[b][t] = s * hg_w[t];
    }
    if (t < 256) {   // content gate: 2 rows per thread (weight reuse)
        const int c = t & 63, rp = t >> 6;
        const int r0 = rp * 2, r1 = r0 + 1;
        const float4* xs4 = (const float4*)xs;
        float l0 = cg_b[c], l1 = l0;
#pragma unroll
        for (int j4 = 0; j4 < 16; ++j4) {
            const float w0 = cg_w[(j4 * 4 + 0) * 64 + c];
            const float w1 = cg_w[(j4 * 4 + 1) * 64 + c];
            const float w2 = cg_w[(j4 * 4 + 2) * 64 + c];
            const float w3 = cg_w[(j4 * 4 + 3) * 64 + c];
            const float4 a0 = xs4[r0 * 16 + j4];
            const float4 a1 = xs4[r1 * 16 + j4];
            l0 = fmaf(a0.x, w0, l0); l0 = fmaf(a0.y, w1, l0);
            l0 = fmaf(a0.z, w2, l0); l0 = fmaf(a0.w, w3, l0);
            l1 = fmaf(a1.x, w0, l1); l1 = fmaf(a1.y, w1, l1);
            l1 = fmaf(a1.z, w2, l1); l1 = fmaf(a1.w, w3, l1);
        }
        xmS[r0 * 64 + c] = (l0 > (float)GATE_THR) ? xs[r0 * 64 + c] : 0.f;
        xmS[r1 * 64 + c] = (l1 > (float)GATE_THR) ? xs[r1 * 64 + c] : 0.f;
    }
    __syncthreads();

    // qkv+gqkv: 192 threads, each 2 adjacent cols x 8 rows (LDS + LDG reuse)
    if (t < 192) {
        const int c = qc;
        const float* bp = isg ? gqkv_b : qkv_b;
        float acc0[RPB], acc1[RPB];
        const float bias0 = bp[c], bias1 = bp[c + 1];
#pragma unroll
        for (int r = 0; r < RPB; ++r) { acc0[r] = bias0; acc1[r] = bias1; }
        const float4* xm4 = (const float4*)xmS;
#pragma unroll
        for (int j4 = 0; j4 < 16; ++j4) {
            const float2 wA = (j4 == 0) ? pwA : *(const float2*)(wp + (j4 * 4 + 0) * 192 + c);
            const float2 wB = (j4 == 0) ? pwB : *(const float2*)(wp + (j4 * 4 + 1) * 192 + c);
            const float2 wC = (j4 == 0) ? pwC : *(const float2*)(wp + (j4 * 4 + 2) * 192 + c);
            const float2 wD = (j4 == 0) ? pwD : *(const float2*)(wp + (j4 * 4 + 3) * 192 + c);
#pragma unroll
            for (int r = 0; r < RPB; ++r) {
                const float4 xv = xm4[r * 16 + j4];
                acc0[r] = fmaf(xv.x, wA.x, acc0[r]); acc1[r] = fmaf(xv.x, wA.y, acc1[r]);
                acc0[r] = fmaf(xv.y, wB.x, acc0[r]); acc1[r] = fmaf(xv.y, wB.y, acc1[r]);
                acc0[r] = fmaf(xv.z, wC.x, acc0[r]); acc1[r] = fmaf(xv.z, wC.y, acc1[r]);
                acc0[r] = fmaf(xv.w, wD.x, acc0[r]); acc1[r] = fmaf(xv.w, wD.y, acc1[r]);
            }
        }
        const int h = c & 63, part = c >> 6;
        if (isg && part == 0) {
#pragma unroll
            for (int r = 0; r < RPB; ++r)
                *(float2*)(gqS + r * 64 + h) = make_float2(acc0[r], acc1[r]);
        } else {
            if (!isg && part == 0) {
#pragma unroll
                for (int r = 0; r < RPB; ++r)
                    *(float2*)(qsS + r * 64 + h) = make_float2(acc0[r], acc1[r]);
            }
            float* d0 = isg ? (part == 1 ? g_gk[h] : g_gv[h])
                            : (part == 0 ? g_q[h] : part == 1 ? g_k[h] : g_v[h]);
            float* d1 = isg ? (part == 1 ? g_gk[h + 1] : g_gv[h + 1])
                            : (part == 0 ? g_q[h + 1] : part == 1 ? g_k[h + 1] : g_v[h + 1]);
            *(float4*)(d0 + n0)     = make_float4(acc0[0], acc0[1], acc0[2], acc0[3]);
            *(float4*)(d0 + n0 + 4) = make_float4(acc0[4], acc0[5], acc0[6], acc0[7]);
            *(float4*)(d1 + n0)     = make_float4(acc1[0], acc1[1], acc1[2], acc1[3]);
            *(float4*)(d1 + n0 + 4) = make_float4(acc1[4], acc1[5], acc1[6], acc1[7]);
        }
    }

    gridbar(0, b & 7);

    // ================= Phase B: head stats (h = b>>1) =================
    const int h = b >> 1, half = b & 1;
    if (t < 256) ((float4*)kk)[t] = ((const float4*)(g_k[h]))[t];
    else         ((float4*)vv)[t - 256] = ((const float4*)(g_v[h]))[t - 256];
    qs[t] = g_q[h][half * 512 + t];

    // ---- stage fuse/proj weights into smem (consumed after bar1) ----
    {
        const float4* fsrc = (const float4*)fus_w;    // 2048 float4
        const float4* psrc = (const float4*)proj_w;   // 1024 float4
        const unsigned fbase = (unsigned)__cvta_generic_to_shared(fusW);
        const unsigned pbase = (unsigned)__cvta_generic_to_shared(projW);
#pragma unroll
        for (int i = 0; i < 4; ++i)
            asm volatile("cp.async.cg.shared.global [%0], [%1], 16;"
                         :: "r"(fbase + (unsigned)(t + i * 512) * 16u),
                            "l"(fsrc + t + i * 512) : "memory");
#pragma unroll
        for (int i = 0; i < 2; ++i)
            asm volatile("cp.async.cg.shared.global [%0], [%1], 16;"
                         :: "r"(pbase + (unsigned)(t + i * 512) * 16u),
                            "l"(psrc + t + i * 512) : "memory");
        asm volatile("cp.async.commit_group;" ::: "memory");
    }
    __syncthreads();

    if (wid < 8) {
        // ---- select: half==0 -> top-20, half==1 -> bottom-20 ----
        const bool isBot = (half == 1);
        unsigned long long key[4];
#pragma unroll
        for (int i = 0; i < 4; ++i) {
            const int m = wid * 128 + i * 32 + lane;
            unsigned f = ford(kk[m]);
            if (isBot) f = ~f;
            key[i] = ((unsigned long long)f << 32) | (unsigned)(1023 - m);
        }
        unsigned long long lb = key[0];
#pragma unroll
        for (int i = 1; i < 4; ++i) if (key[i] > lb) lb = key[i];
        for (int it = 0; it < 20; ++it) {
            const unsigned bh = (unsigned)(lb >> 32);
            const unsigned bl = (unsigned)lb;
            const unsigned wbh = __reduce_max_sync(0xffffffffu, bh);
            const unsigned wbl = __reduce_max_sync(0xffffffffu, (bh == wbh) ? bl : 0u);
            if (bh == wbh && bl == wbl) {
#pragma unroll
                for (int i = 0; i < 4; ++i) if (key[i] == lb) key[i] = 0ull;
                lb = key[0];
#pragma unroll
                for (int i = 1; i < 4; ++i) if (key[i] > lb) lb = key[i];
            }
            if (lane == 0) candS[wid * 20 + it] = ((unsigned long long)wbh << 32) | wbl;
        }
    } else {
        // ---- moments: 256 threads x 4 elements ----
        // M (k powers) in both halves; half==0 additionally Wg, half==1 Mg.
        const int u = t - 256;
        float M[NC + 1];
#pragma unroll
        for (int j = 0; j < NC + 1; ++j) M[j] = 0.f;
        float G[NC];
#pragma unroll
        for (int j = 0; j < NC; ++j) G[j] = 0.f;
        {
            const float4 k4 = ((const float4*)kk)[u];
            const float e[4] = {k4.x, k4.y, k4.z, k4.w};
#pragma unroll
            for (int q4 = 0; q4 < 4; ++q4) {
                float p = 1.f;
#pragma unroll
                for (int j = 0; j < NC + 1; ++j) { M[j] += p; p *= e[q4]; }
            }
        }
        {
            const float4 gk4 = ((const float4*)(g_gk[h]))[u];
            const float ek[4] = {gk4.x, gk4.y, gk4.z, gk4.w};
            if (half == 0) {   // Wg = sum gv * gk^j
                const float4 gv4 = ((const float4*)(g_gv[h]))[u];
                const float ev[4] = {gv4.x, gv4.y, gv4.z, gv4.w};
#pragma unroll
                for (int q4 = 0; q4 < 4; ++q4) {
                    float p = ev[q4];
#pragma unroll
                    for (int j = 0; j < NC; ++j) { G[j] += p; p *= ek[q4]; }
                }
            } else {           // Mg = sum gk^j
#pragma unroll
                for (int q4 = 0; q4 < 4; ++q4) {
                    float p = 1.f;
#pragma unroll
                    for (int j = 0; j < NC; ++j) { G[j] += p; p *= ek[q4]; }
                }
            }
        }
#pragma unroll
        for (int j = 0; j < NC + 1; ++j) {
            float v = M[j];
            for (int o = 16; o; o >>= 1) v += __shfl_down_sync(0xffffffffu, v, o);
            if (lane == 0) red[j][wid - 8] = v;
        }
#pragma unroll
        for (int j = 0; j < NC; ++j) {
            float v = G[j];
            for (int o = 16; o; o >>= 1) v += __shfl_down_sync(0xffffffffu, v, o);
            if (lane == 0) red[NC + 1 + j][wid - 8] = v;
        }
    }
    __syncthreads();

    if (wid == 0) {
        // ---- merge 160 candidates + inline numerator-coefficient build ----
        unsigned long long k0 = candS[lane];
        unsigned long long k1 = candS[lane + 32];
        unsigned long long k2 = candS[lane + 64];
        unsigned long long k3 = candS[lane + 96];
        unsigned long long k4 = candS[lane + 128];
        unsigned long long mb = k0;
        if (k1 > mb) mb = k1;
        if (k2 > mb) mb = k2;
        if (k3 > mb) mb = k3;
        if (k4 > mb) mb = k4;
        float cl0 = 0.f, cl1 = 0.f, cl2 = 0.f, cl3 = 0.f,
              cl4 = 0.f, cl5 = 0.f, cl6 = 0.f, cl7 = 0.f;
        for (int it = 0; it < 20; ++it) {
            const unsigned bh = (unsigned)(mb >> 32);
            const unsigned bl = (unsigned)mb;
            const unsigned wbh = __reduce_max_sync(0xffffffffu, bh);
            const unsigned wbl = __reduce_max_sync(0xffffffffu, (bh == wbh) ? bl : 0u);
            if (bh == wbh && bl == wbl) {
                if (k0 == mb) k0 = 0ull;
                if (k1 == mb) k1 = 0ull;
                if (k2 == mb) k2 = 0ull;
                if (k3 == mb) k3 = 0ull;
                if (k4 == mb) k4 = 0ull;
                mb = k0;
                if (k1 > mb) mb = k1;
                if (k2 > mb) mb = k2;
                if (k3 > mb) mb = k3;
                if (k4 > mb) mb = k4;
            }
            const int m = 1023 - (int)wbl;
            const float kv = kk[m], vl = vv[m];   // broadcast LDS
            float p = vl;
            cl0 += p; p *= kv; cl1 += p; p *= kv; cl2 += p; p *= kv;
            cl3 += p; p *= kv; cl4 += p; p *= kv; cl5 += p; p *= kv;
            cl6 += p; p *= kv; cl7 += p;
            if (lane == 0) { selK[it] = kv; selV[it] = vl; }
        }
        __syncwarp();
        if (lane == 0) {
            float* dst = (half == 0) ? g_cLp[h] : g_cLn[h];
            dst[0] = cl0 * c_invf[0]; dst[1] = cl1 * c_invf[1];
            dst[2] = cl2 * c_invf[2]; dst[3] = cl3 * c_invf[3];
            dst[4] = cl4 * c_invf[4]; dst[5] = cl5 * c_invf[5];
            dst[6] = cl6 * c_invf[6]; dst[7] = cl7 * c_invf[7];
        }
        if (lane < KMAX) {   // slow-path data
            if (half == 0) { g_tkT[lane][h] = selK[lane]; g_tvT[lane][h] = selV[lane]; }
            else           { g_bkT[lane][h] = selK[lane]; g_bvT[lane][h] = selV[lane]; }
        }
    } else {
        if (wid == 1) {
            if (lane < 17) {
                float s = 0.f;
#pragma unroll
                for (int w = 0; w < 8; ++w) s += red[lane][w];
                Rall[lane] = s;
            }
            __syncwarp();
            if (lane < NC) {
                const float f = c_invf[lane];
                coefD[lane]  = Rall[lane] * f;
                coefS1[lane] = Rall[lane + 1] * f;
                if (half == 0) {
                    g_hdD[h][lane]  = Rall[lane] * f;
                    g_hdSv[h][lane] = Rall[NC + 1 + lane] * f;   // from Wg
                } else {
                    g_hdDg[h][lane] = Rall[NC + 1 + lane] * f;   // from Mg
                }
            }
        }
        // warps 1..15 sync (480 threads) -> coefD visible -> entropy
        asm volatile("bar.sync 1, 480;" ::: "memory");
        const int u = t - 32;            // 0..479
        float ent;
        {
            const float a = qs[u] * SCALE;
            const float D = horner8(coefD, a);
            const float S1 = horner8(coefS1, a);
            ent = __logf(D) - a * S1 / D;
        }
        if (t >= 480) {                  // rows 480..511 (warp 15, extra row)
            const float a = qs[u + 32] * SCALE;
            const float D = horner8(coefD, a);
            const float S1 = horner8(coefS1, a);
            ent += __logf(D) - a * S1 / D;
        }
        for (int o = 16; o; o >>= 1) ent += __shfl_down_sync(0xffffffffu, ent, o);
        if (lane == 0) red[0][wid] = ent;
        if (half == 1 && t == 448) {     // vpre, concurrent with merge tail
            float s = 0.f;
            for (int i = 0; i < KMAX; ++i) { s += vv[i]; g_vpreT[i][h] = s; }
        }
    }
    __syncthreads();
    if (t == 0) {
        float s = 0.f;
#pragma unroll
        for (int w = 1; w < 16; ++w) s += red[0][w];
        g_entpart[b] = s;
    }

    gridbar(1, b & 7);

    // ================= Phase C: km, gx, local attn, fuse, proj =================
    if (wid == 0) {   // km: fixed-order, identical in every block
        const float4 e4 = ((const float4*)g_entpart)[lane];
        float s = e4.x + e4.y + e4.z + e4.w;
        for (int o = 16; o; o >>= 1) s += __shfl_down_sync(0xffffffffu, s, o);
        if (lane == 0) {
            const float em = s * (1.f / (float)(NH * NN));
            int km = 5 + (int)rintf(15.f * em);
            if (km < 5) km = 5;
            if (km > 20) km = 20;
            km_s = km;
        }
    }
    {   // load the 5 per-head coef tables (coalesced, padded smem)
        const int hh = t >> 3, j = t & 7;
        const int d = hh * NCP + j;
        cDs[d]  = (&g_hdD[0][0])[t];
        cDgS[d] = (&g_hdDg[0][0])[t];
        cSvS[d] = (&g_hdSv[0][0])[t];
        cLp[d]  = (&g_cLp[0][0])[t];
        cLn[d]  = (&g_cLn[0][0])[t];
    }
    {   // importance: flat weighted sum of g_xpart (pre-scaled by hg_w)
        const float4* xp4 = (const float4*)&g_xpart[0][0];
        float s = 0.f;
#pragma unroll
        for (int i = 0; i < 4; ++i) {
            const float4 v = xp4[t * 4 + i];
            s += (v.x + v.y) + (v.z + v.w);
        }
        for (int o = 16; o; o >>= 1) s += __shfl_down_sync(0xffffffffu, s, o);
        if (lane == 0) impred[wid] = s;
    }
    __syncthreads();
    const int km = km_s;

    if (km != KMAX) {   // slow path (uniform branch; never taken for this data)
        if (t >= 128 && t < 256) {
            const int u = t - 128;
            const int hh = u & 63;
            const bool isBot = (u >= 64);
            float cl[NC];
#pragma unroll
            for (int j = 0; j < NC; ++j) cl[j] = 0.f;
            for (int i = 0; i < km; ++i) {
                const float kv = isBot ? g_bkT[i][hh] : g_tkT[i][hh];
                float p       = isBot ? g_bvT[i][hh] : g_tvT[i][hh];
#pragma unroll
                for (int j = 0; j < NC; ++j) { cl[j] += p; p *= kv; }
            }
            float* dst = (isBot ? cLn : cLp) + hh * NCP;
#pragma unroll
            for (int j = 0; j < NC; ++j) dst[j] = cl[j] * c_invf[j];
        }
        __syncthreads();
    }

    if (t == 448) {
        float l = hg_b[0];
#pragma unroll
        for (int w = 0; w < 16; ++w) l += impred[w] * (1.f / (float)NN);
        const float imp = 1.f / (1.f + expf(-l));
        early_s = (imp < 0.1f) ? 1 : 0;
    }
    {   // gx (1/thread), from block-local gqS
        const int hh = t & 63;
        const float ag = gqS[t] * SCALE;
        gxS[t] = horner8(cSvS + hh * NCP, ag) / horner8(cDgS + hh * NCP, ag);
    }
    // local attention (1/thread)
    {
        const int hh = t & 63;
        const float a = qsS[t] * SCALE;
        const float D = horner8(cDs + hh * NCP, a);
        float num;
        if (a > 0.f)      num = horner8(cLp + hh * NCP, a);
        else if (a < 0.f) num = horner8(cLn + hh * NCP, a);
        else              num = g_vpreT[km - 1][hh];
        lxS[t] = num / D;
    }
    asm volatile("cp.async.wait_group 0;" ::: "memory");
    __syncthreads();

    // fuse: 256 threads x 2 rows (weights from smem)
    if (t < 256) {
        const int c = t & 63, rp = t >> 6;
        const int r0 = rp * 2, r1 = r0 + 1;
        const float4* lx4 = (const float4*)lxS;
        const float4* gx4 = (const float4*)gxS;
        float f0 = fus_b[c], f1 = f0;
#pragma unroll
        for (int j4 = 0; j4 < 16; ++j4) {
            const float w0 = fusW[(j4 * 4 + 0) * 64 + c];
            const float w1 = fusW[(j4 * 4 + 1) * 64 + c];
            const float w2 = fusW[(j4 * 4 + 2) * 64 + c];
            const float w3 = fusW[(j4 * 4 + 3) * 64 + c];
            const float4 a0 = lx4[r0 * 16 + j4];
            const float4 a1 = lx4[r1 * 16 + j4];
            f0 = fmaf(a0.x, w0, f0); f0 = fmaf(a0.y, w1, f0);
            f0 = fmaf(a0.z, w2, f0); f0 = fmaf(a0.w, w3, f0);
            f1 = fmaf(a1.x, w0, f1); f1 = fmaf(a1.y, w1, f1);
            f1 = fmaf(a1.z, w2, f1); f1 = fmaf(a1.w, w3, f1);
        }
#pragma unroll
        for (int j4 = 0; j4 < 16; ++j4) {
            const float w0 = fusW[(64 + j4 * 4 + 0) * 64 + c];
            const float w1 = fusW[(64 + j4 * 4 + 1) * 64 + c];
            const float w2 = fusW[(64 + j4 * 4 + 2) * 64 + c];
            const float w3 = fusW[(64 + j4 * 4 + 3) * 64 + c];
            const float4 a0 = gx4[r0 * 16 + j4];
            const float4 a1 = gx4[r1 * 16 + j4];
            f0 = fmaf(a0.x, w0, f0); f0 = fmaf(a0.y, w1, f0);
            f0 = fmaf(a0.z, w2, f0); f0 = fmaf(a0.w, w3, f0);
            f1 = fmaf(a1.x, w0, f1); f1 = fmaf(a1.y, w1, f1);
            f1 = fmaf(a1.z, w2, f1); f1 = fmaf(a1.w, w3, f1);
        }
        ttS[r0 * 64 + c] = xmS[r0 * 64 + c] + f0;
        ttS[r1 * 64 + c] = xmS[r1 * 64 + c] + f1;
    }
    __syncthreads();
    const int early = early_s;
    if (t < 256) {   // proj: 2 rows per thread (weights from smem)
        const int c = t & 63, rp = t >> 6;
        const int r0 = rp * 2, r1 = r0 + 1;
        const float4* tt4 = (const float4*)ttS;
        float o0 = proj_b[c], o1 = o0;
#pragma unroll
        for (int j4 = 0; j4 < 16; ++j4) {
            const float w0 = projW[(j4 * 4 + 0) * 64 + c];
            const float w1 = projW[(j4 * 4 + 1) * 64 + c];
            const float w2 = projW[(j4 * 4 + 2) * 64 + c];
            const float w3 = projW[(j4 * 4 + 3) * 64 + c];
            const float4 a0 = tt4[r0 * 16 + j4];
            const float4 a1 = tt4[r1 * 16 + j4];
            o0 = fmaf(a0.x, w0, o0); o0 = fmaf(a0.y, w1, o0);
            o0 = fmaf(a0.z, w2, o0); o0 = fmaf(a0.w, w3, o0);
            o1 = fmaf(a1.x, w0, o1); o1 = fmaf(a1.y, w1, o1);
            o1 = fmaf(a1.z, w2, o1); o1 = fmaf(a1.w, w3, o1);
        }
        out[(n0 + r0) * 64 + c] = early ? xs[r0 * 64 + c] : o0;
        out[(n0 + r1) * 64 + c] = early ? xs[r1 * 64 + c] : o1;
    }
}

extern "C" void kernel_launch(void* const* d_in, const int* in_sizes, int n_in,
                              void* d_out, int out_size) {
    const float* x      = (const float*)d_in[0];
    const float* qkv_w  = (const float*)d_in[1];
    const float* qkv_b  = (const float*)d_in[2];
    const float* gqkv_w = (const float*)d_in[3];
    const float* gqkv_b = (const float*)d_in[4];
    const float* cg_w   = (const float*)d_in[5];
    const float* cg_b   = (const float*)d_in[6];
    const float* hg_w   = (const float*)d_in[7];
    const float* hg_b   = (const float*)d_in[8];
    const float* fus_w  = (const float*)d_in[9];
    const float* fus_b  = (const float*)d_in[10];
    const float* proj_w = (const float*)d_in[11];
    const float* proj_b = (const float*)d_in[12];
    float* out = (float*)d_out;

    // opt-in for static+dynamic smem > 48KB (idempotent host call; not a
    // stream op, not an allocation -> graph-capture safe)
    cudaFuncSetAttribute(fused_kernel,
                         cudaFuncAttributeMaxDynamicSharedMemorySize, 49152);

    fused_kernel<<<NB, NT, 49152>>>(x, qkv_w, qkv_b, gqkv_w, gqkv_b, cg_w, cg_b,
                                    hg_w, hg_b, fus_w, fus_b, proj_w, proj_b, out);
}

// round 16
// speedup vs baseline: 1.1969x; 1.1969x over previous
#include <cuda_runtime.h>
#include <math.h>

#define NN 1024
#define NH 64
#define NC 8              // Taylor terms (degree 7)
#define NCP 9             // padded stride (odd -> conflict-free)
#define SCALE 0.125f
#define KMAX 20
#define NB 128
#define NT 512
#define RPB 8
#define GATE_THR (-2.1972245773362196f)   // logit(0.1)

// -------- device scratch --------
__device__ float g_q[NH][NN], g_k[NH][NN], g_v[NH][NN];
__device__ float g_gk[NH][NN], g_gv[NH][NN];
__device__ __align__(16) float g_xpart[NB][64];   // colsum * hg_w (flat-summable)
__device__ __align__(16) float g_entpart[NB];
__device__ float g_hdD[NH][NC], g_hdDg[NH][NC], g_hdSv[NH][NC];
__device__ float g_cLp[NH][NC], g_cLn[NH][NC];   // local-numerator coefs (km==KMAX)
__device__ __align__(16) float g_tkT[KMAX][NH];  // slow path (km != KMAX)
__device__ __align__(16) float g_tvT[KMAX][NH];
__device__ __align__(16) float g_bkT[KMAX][NH];
__device__ __align__(16) float g_bvT[KMAX][NH];
__device__ float g_vpreT[KMAX][NH];
__device__ unsigned g_barcnt[4];      // zero-init; monotonic across replays

__constant__ float c_invf[NC] = {
    1.0f, 1.0f, 0.5f, 1.66666672e-01f, 4.16666679e-02f, 8.33333377e-03f,
    1.38888892e-03f, 1.98412701e-04f };

__device__ __forceinline__ unsigned ford(float f) {
    unsigned u = __float_as_uint(f);
    return (u & 0x80000000u) ? ~u : (u | 0x80000000u);
}

__device__ __forceinline__ float horner8(const float* c, float a) {
    float r = c[NC - 1];
#pragma unroll
    for (int j = NC - 2; j >= 0; --j) r = fmaf(r, a, c[j]);
    return r;
}

// grid barrier: single counter, release-atomic + acquire-load spin
__device__ __forceinline__ void gridbar(int idx) {
    __syncthreads();
    if (threadIdx.x == 0) {
        unsigned* addr = &g_barcnt[idx];
        unsigned my;
        asm volatile("atom.release.gpu.global.add.u32 %0, [%1], 1;"
                     : "=r"(my) : "l"(addr) : "memory");
        const unsigned target = (my / (unsigned)NB + 1u) * (unsigned)NB;
        unsigned cur;
        do {
            asm volatile("ld.acquire.gpu.global.u32 %0, [%1];"
                         : "=r"(cur) : "l"(addr) : "memory");
        } while (cur < target);
    }
    __syncthreads();
}

__global__ __launch_bounds__(NT, 1)
void fused_kernel(const float* __restrict__ x,
                  const float* __restrict__ qkv_w,  const float* __restrict__ qkv_b,
                  const float* __restrict__ gqkv_w, const float* __restrict__ gqkv_b,
                  const float* __restrict__ cg_w,   const float* __restrict__ cg_b,
                  const float* __restrict__ hg_w,   const float* __restrict__ hg_b,
                  const float* __restrict__ fus_w,  const float* __restrict__ fus_b,
                  const float* __restrict__ proj_w, const float* __restrict__ proj_b,
                  float* __restrict__ out) {
    extern __shared__ __align__(16) float dynS[];   // [8192] fus_w, [4096] proj_w
    float* fusW  = dynS;
    float* projW = dynS + 8192;

    __shared__ __align__(16) float xs[512], xmS[512], qsS[512], gqS[512]; // persist A->C
    __shared__ __align__(16) float kk[NN], vv[NN];
    __shared__ __align__(16) float qs[512];
    __shared__ __align__(16) float cDs[64 * NCP], cDgS[64 * NCP], cSvS[64 * NCP];
    __shared__ __align__(16) float cLp[64 * NCP], cLn[64 * NCP];
    __shared__ __align__(16) float lxS[512], gxS[512], ttS[512];
    __shared__ unsigned long long candS[160];
    __shared__ float red[17][16];
    __shared__ float Rall[17];
    __shared__ float coefD[NC], coefS1[NC];
    __shared__ float selK[KMAX], selV[KMAX];
    __shared__ float impred[16];
    __shared__ int   km_s, early_s;

    const int b = blockIdx.x;
    const int t = threadIdx.x;
    const int lane = t & 31, wid = t >> 5;
    const int n0 = b * RPB;

    // ================= Phase A: gate + qkv/gqkv GEMMs (8 rows) =================
    xs[t] = x[n0 * 64 + t];            // RPB*64 == NT

    // prefetch qkv/gqkv j4==0 weight group (independent of x / gate)
    float2 pwA, pwB, pwC, pwD;
    const bool isg = (t >= 96) && (t < 192);
    const int qc = (t < 192) ? ((isg ? (t - 96) : t) * 2) : 0;
    const float* wp = isg ? gqkv_w : qkv_w;
    if (t < 192) {
        pwA = *(const float2*)(wp + 0 * 192 + qc);
        pwB = *(const float2*)(wp + 1 * 192 + qc);
        pwC = *(const float2*)(wp + 2 * 192 + qc);
        pwD = *(const float2*)(wp + 3 * 192 + qc);
    }
    __syncthreads();

    if (t < 64) {   // column sum pre-scaled by hg_w (flat-summable later)
        float s = 0.f;
#pragma unroll
        for (int r = 0; r < RPB; ++r) s += xs[r * 64 + t];
        g_xpart[b][t] = s * hg_w[t];
    }
    if (t < 256) {   // content gate: 2 rows per thread (weight reuse)
        const int c = t & 63, rp = t >> 6;
        const int r0 = rp * 2, r1 = r0 + 1;
        const float4* xs4 = (const float4*)xs;
        float l0 = cg_b[c], l1 = l0;
#pragma unroll
        for (int j4 = 0; j4 < 16; ++j4) {
            const float w0 = cg_w[(j4 * 4 + 0) * 64 + c];
            const float w1 = cg_w[(j4 * 4 + 1) * 64 + c];
            const float w2 = cg_w[(j4 * 4 + 2) * 64 + c];
            const float w3 = cg_w[(j4 * 4 + 3) * 64 + c];
            const float4 a0 = xs4[r0 * 16 + j4];
            const float4 a1 = xs4[r1 * 16 + j4];
            l0 = fmaf(a0.x, w0, l0); l0 = fmaf(a0.y, w1, l0);
            l0 = fmaf(a0.z, w2, l0); l0 = fmaf(a0.w, w3, l0);
            l1 = fmaf(a1.x, w0, l1); l1 = fmaf(a1.y, w1, l1);
            l1 = fmaf(a1.z, w2, l1); l1 = fmaf(a1.w, w3, l1);
        }
        xmS[r0 * 64 + c] = (l0 > (float)GATE_THR) ? xs[r0 * 64 + c] : 0.f;
        xmS[r1 * 64 + c] = (l1 > (float)GATE_THR) ? xs[r1 * 64 + c] : 0.f;
    }
    __syncthreads();

    // qkv+gqkv: 192 threads, each 2 adjacent cols x 8 rows (LDS + LDG reuse)
    if (t < 192) {
        const int c = qc;
        const float* bp = isg ? gqkv_b : qkv_b;
        float acc0[RPB], acc1[RPB];
        const float bias0 = bp[c], bias1 = bp[c + 1];
#pragma unroll
        for (int r = 0; r < RPB; ++r) { acc0[r] = bias0; acc1[r] = bias1; }
        const float4* xm4 = (const float4*)xmS;
#pragma unroll
        for (int j4 = 0; j4 < 16; ++j4) {
            const float2 wA = (j4 == 0) ? pwA : *(const float2*)(wp + (j4 * 4 + 0) * 192 + c);
            const float2 wB = (j4 == 0) ? pwB : *(const float2*)(wp + (j4 * 4 + 1) * 192 + c);
            const float2 wC = (j4 == 0) ? pwC : *(const float2*)(wp + (j4 * 4 + 2) * 192 + c);
            const float2 wD = (j4 == 0) ? pwD : *(const float2*)(wp + (j4 * 4 + 3) * 192 + c);
#pragma unroll
            for (int r = 0; r < RPB; ++r) {
                const float4 xv = xm4[r * 16 + j4];
                acc0[r] = fmaf(xv.x, wA.x, acc0[r]); acc1[r] = fmaf(xv.x, wA.y, acc1[r]);
                acc0[r] = fmaf(xv.y, wB.x, acc0[r]); acc1[r] = fmaf(xv.y, wB.y, acc1[r]);
                acc0[r] = fmaf(xv.z, wC.x, acc0[r]); acc1[r] = fmaf(xv.z, wC.y, acc1[r]);
                acc0[r] = fmaf(xv.w, wD.x, acc0[r]); acc1[r] = fmaf(xv.w, wD.y, acc1[r]);
            }
        }
        const int h = c & 63, part = c >> 6;
        if (isg && part == 0) {
#pragma unroll
            for (int r = 0; r < RPB; ++r)
                *(float2*)(gqS + r * 64 + h) = make_float2(acc0[r], acc1[r]);
        } else {
            if (!isg && part == 0) {
#pragma unroll
                for (int r = 0; r < RPB; ++r)
                    *(float2*)(qsS + r * 64 + h) = make_float2(acc0[r], acc1[r]);
            }
            float* d0 = isg ? (part == 1 ? g_gk[h] : g_gv[h])
                            : (part == 0 ? g_q[h] : part == 1 ? g_k[h] : g_v[h]);
            float* d1 = isg ? (part == 1 ? g_gk[h + 1] : g_gv[h + 1])
                            : (part == 0 ? g_q[h + 1] : part == 1 ? g_k[h + 1] : g_v[h + 1]);
            *(float4*)(d0 + n0)     = make_float4(acc0[0], acc0[1], acc0[2], acc0[3]);
            *(float4*)(d0 + n0 + 4) = make_float4(acc0[4], acc0[5], acc0[6], acc0[7]);
            *(float4*)(d1 + n0)     = make_float4(acc1[0], acc1[1], acc1[2], acc1[3]);
            *(float4*)(d1 + n0 + 4) = make_float4(acc1[4], acc1[5], acc1[6], acc1[7]);
        }
    }

    gridbar(0);

    // ================= Phase B: head stats (h = b>>1) =================
    const int h = b >> 1, half = b & 1;
    if (t < 256) ((float4*)kk)[t] = ((const float4*)(g_k[h]))[t];
    else         ((float4*)vv)[t - 256] = ((const float4*)(g_v[h]))[t - 256];
    qs[t] = g_q[h][half * 512 + t];

    // ---- stage fuse/proj weights into smem (consumed after bar1) ----
    {
        const float4* fsrc = (const float4*)fus_w;    // 2048 float4
        const float4* psrc = (const float4*)proj_w;   // 1024 float4
        const unsigned fbase = (unsigned)__cvta_generic_to_shared(fusW);
        const unsigned pbase = (unsigned)__cvta_generic_to_shared(projW);
#pragma unroll
        for (int i = 0; i < 4; ++i)
            asm volatile("cp.async.cg.shared.global [%0], [%1], 16;"
                         :: "r"(fbase + (unsigned)(t + i * 512) * 16u),
                            "l"(fsrc + t + i * 512) : "memory");
#pragma unroll
        for (int i = 0; i < 2; ++i)
            asm volatile("cp.async.cg.shared.global [%0], [%1], 16;"
                         :: "r"(pbase + (unsigned)(t + i * 512) * 16u),
                            "l"(psrc + t + i * 512) : "memory");
        asm volatile("cp.async.commit_group;" ::: "memory");
    }
    __syncthreads();

    if (wid < 8) {
        // ---- select: half==0 -> top-20, half==1 -> bottom-20 ----
        const bool isBot = (half == 1);
        unsigned long long key[4];
#pragma unroll
        for (int i = 0; i < 4; ++i) {
            const int m = wid * 128 + i * 32 + lane;
            unsigned f = ford(kk[m]);
            if (isBot) f = ~f;
            key[i] = ((unsigned long long)f << 32) | (unsigned)(1023 - m);
        }
        unsigned long long lb = key[0];
#pragma unroll
        for (int i = 1; i < 4; ++i) if (key[i] > lb) lb = key[i];
        for (int it = 0; it < 20; ++it) {
            const unsigned bh = (unsigned)(lb >> 32);
            const unsigned bl = (unsigned)lb;
            const unsigned wbh = __reduce_max_sync(0xffffffffu, bh);
            const unsigned wbl = __reduce_max_sync(0xffffffffu, (bh == wbh) ? bl : 0u);
            if (bh == wbh && bl == wbl) {
#pragma unroll
                for (int i = 0; i < 4; ++i) if (key[i] == lb) key[i] = 0ull;
                lb = key[0];
#pragma unroll
                for (int i = 1; i < 4; ++i) if (key[i] > lb) lb = key[i];
            }
            if (lane == 0) candS[wid * 20 + it] = ((unsigned long long)wbh << 32) | wbl;
        }
    } else {
        // ---- moments: 256 threads x 4 elements ----
        // M (k powers) in both halves; half==0 additionally Wg, half==1 Mg.
        const int u = t - 256;
        float M[NC + 1];
#pragma unroll
        for (int j = 0; j < NC + 1; ++j) M[j] = 0.f;
        float G[NC];
#pragma unroll
        for (int j = 0; j < NC; ++j) G[j] = 0.f;
        {
            const float4 k4 = ((const float4*)kk)[u];
            const float e[4] = {k4.x, k4.y, k4.z, k4.w};
#pragma unroll
            for (int q4 = 0; q4 < 4; ++q4) {
                float p = 1.f;
#pragma unroll
                for (int j = 0; j < NC + 1; ++j) { M[j] += p; p *= e[q4]; }
            }
        }
        {
            const float4 gk4 = ((const float4*)(g_gk[h]))[u];
            const float ek[4] = {gk4.x, gk4.y, gk4.z, gk4.w};
            if (half == 0) {   // Wg = sum gv * gk^j
                const float4 gv4 = ((const float4*)(g_gv[h]))[u];
                const float ev[4] = {gv4.x, gv4.y, gv4.z, gv4.w};
#pragma unroll
                for (int q4 = 0; q4 < 4; ++q4) {
                    float p = ev[q4];
#pragma unroll
                    for (int j = 0; j < NC; ++j) { G[j] += p; p *= ek[q4]; }
                }
            } else {           // Mg = sum gk^j
#pragma unroll
                for (int q4 = 0; q4 < 4; ++q4) {
                    float p = 1.f;
#pragma unroll
                    for (int j = 0; j < NC; ++j) { G[j] += p; p *= ek[q4]; }
                }
            }
        }
#pragma unroll
        for (int j = 0; j < NC + 1; ++j) {
            float v = M[j];
            for (int o = 16; o; o >>= 1) v += __shfl_down_sync(0xffffffffu, v, o);
            if (lane == 0) red[j][wid - 8] = v;
        }
#pragma unroll
        for (int j = 0; j < NC; ++j) {
            float v = G[j];
            for (int o = 16; o; o >>= 1) v += __shfl_down_sync(0xffffffffu, v, o);
            if (lane == 0) red[NC + 1 + j][wid - 8] = v;
        }
    }
    __syncthreads();

    if (wid == 0) {
        // ---- merge 160 candidates + inline numerator-coefficient build ----
        unsigned long long k0 = candS[lane];
        unsigned long long k1 = candS[lane + 32];
        unsigned long long k2 = candS[lane + 64];
        unsigned long long k3 = candS[lane + 96];
        unsigned long long k4 = candS[lane + 128];
        unsigned long long mb = k0;
        if (k1 > mb) mb = k1;
        if (k2 > mb) mb = k2;
        if (k3 > mb) mb = k3;
        if (k4 > mb) mb = k4;
        float cl0 = 0.f, cl1 = 0.f, cl2 = 0.f, cl3 = 0.f,
              cl4 = 0.f, cl5 = 0.f, cl6 = 0.f, cl7 = 0.f;
        for (int it = 0; it < 20; ++it) {
            const unsigned bh = (unsigned)(mb >> 32);
            const unsigned bl = (unsigned)mb;
            const unsigned wbh = __reduce_max_sync(0xffffffffu, bh);
            const unsigned wbl = __reduce_max_sync(0xffffffffu, (bh == wbh) ? bl : 0u);
            if (bh == wbh && bl == wbl) {
                if (k0 == mb) k0 = 0ull;
                if (k1 == mb) k1 = 0ull;
                if (k2 == mb) k2 = 0ull;
                if (k3 == mb) k3 = 0ull;
                if (k4 == mb) k4 = 0ull;
                mb = k0;
                if (k1 > mb) mb = k1;
                if (k2 > mb) mb = k2;
                if (k3 > mb) mb = k3;
                if (k4 > mb) mb = k4;
            }
            const int m = 1023 - (int)wbl;
            const float kv = kk[m], vl = vv[m];   // broadcast LDS
            float p = vl;
            cl0 += p; p *= kv; cl1 += p; p *= kv; cl2 += p; p *= kv;
            cl3 += p; p *= kv; cl4 += p; p *= kv; cl5 += p; p *= kv;
            cl6 += p; p *= kv; cl7 += p;
            if (lane == 0) { selK[it] = kv; selV[it] = vl; }
        }
        __syncwarp();
        if (lane == 0) {
            float* dst = (half == 0) ? g_cLp[h] : g_cLn[h];
            dst[0] = cl0 * c_invf[0]; dst[1] = cl1 * c_invf[1];
            dst[2] = cl2 * c_invf[2]; dst[3] = cl3 * c_invf[3];
            dst[4] = cl4 * c_invf[4]; dst[5] = cl5 * c_invf[5];
            dst[6] = cl6 * c_invf[6]; dst[7] = cl7 * c_invf[7];
        }
        if (lane < KMAX) {   // slow-path data
            if (half == 0) { g_tkT[lane][h] = selK[lane]; g_tvT[lane][h] = selV[lane]; }
            else           { g_bkT[lane][h] = selK[lane]; g_bvT[lane][h] = selV[lane]; }
        }
    } else {
        if (wid == 1) {
            if (lane < 17) {
                float s = 0.f;
#pragma unroll
                for (int w = 0; w < 8; ++w) s += red[lane][w];
                Rall[lane] = s;
            }
            __syncwarp();
            if (lane < NC) {
                const float f = c_invf[lane];
                coefD[lane]  = Rall[lane] * f;
                coefS1[lane] = Rall[lane + 1] * f;
                if (half == 0) {
                    g_hdD[h][lane]  = Rall[lane] * f;
                    g_hdSv[h][lane] = Rall[NC + 1 + lane] * f;   // from Wg
                } else {
                    g_hdDg[h][lane] = Rall[NC + 1 + lane] * f;   // from Mg
                }
            }
        }
        // warps 1..15 sync (480 threads) -> coefD visible -> entropy
        asm volatile("bar.sync 1, 480;" ::: "memory");
        const int u = t - 32;            // 0..479
        float ent;
        {
            const float a = qs[u] * SCALE;
            const float D = horner8(coefD, a);
            const float S1 = horner8(coefS1, a);
            ent = __logf(D) - a * S1 / D;
        }
        if (t >= 480) {                  // rows 480..511 (warp 15, extra row)
            const float a = qs[u + 32] * SCALE;
            const float D = horner8(coefD, a);
            const float S1 = horner8(coefS1, a);
            ent += __logf(D) - a * S1 / D;
        }
        for (int o = 16; o; o >>= 1) ent += __shfl_down_sync(0xffffffffu, ent, o);
        if (lane == 0) red[0][wid] = ent;
        if (half == 1 && t == 448) {     // vpre, concurrent with merge tail
            float s = 0.f;
            for (int i = 0; i < KMAX; ++i) { s += vv[i]; g_vpreT[i][h] = s; }
        }
    }
    __syncthreads();
    if (t == 0) {
        float s = 0.f;
#pragma unroll
        for (int w = 1; w < 16; ++w) s += red[0][w];
        g_entpart[b] = s;
    }

    gridbar(1);

    // ================= Phase C: km, gx, local attn, fuse, proj =================
    if (wid == 0) {   // km: fixed-order, identical in every block
        const float4 e4 = ((const float4*)g_entpart)[lane];
        float s = e4.x + e4.y + e4.z + e4.w;
        for (int o = 16; o; o >>= 1) s += __shfl_down_sync(0xffffffffu, s, o);
        if (lane == 0) {
            const float em = s * (1.f / (float)(NH * NN));
            int km = 5 + (int)rintf(15.f * em);
            if (km < 5) km = 5;
            if (km > 20) km = 20;
            km_s = km;
        }
    }
    {   // load the 5 per-head coef tables (coalesced, padded smem)
        const int hh = t >> 3, j = t & 7;
        const int d = hh * NCP + j;
        cDs[d]  = (&g_hdD[0][0])[t];
        cDgS[d] = (&g_hdDg[0][0])[t];
        cSvS[d] = (&g_hdSv[0][0])[t];
        cLp[d]  = (&g_cLp[0][0])[t];
        cLn[d]  = (&g_cLn[0][0])[t];
    }
    {   // importance: flat weighted sum of g_xpart (pre-scaled by hg_w)
        const float4* xp4 = (const float4*)&g_xpart[0][0];
        float s = 0.f;
#pragma unroll
        for (int i = 0; i < 4; ++i) {
            const float4 v = xp4[t * 4 + i];
            s += (v.x + v.y) + (v.z + v.w);
        }
        for (int o = 16; o; o >>= 1) s += __shfl_down_sync(0xffffffffu, s, o);
        if (lane == 0) impred[wid] = s;
    }
    __syncthreads();
    const int km = km_s;

    if (km != KMAX) {   // slow path (uniform branch; never taken for this data)
        if (t >= 128 && t < 256) {
            const int u = t - 128;
            const int hh = u & 63;
            const bool isBot = (u >= 64);
            float cl[NC];
#pragma unroll
            for (int j = 0; j < NC; ++j) cl[j] = 0.f;
            for (int i = 0; i < km; ++i) {
                const float kv = isBot ? g_bkT[i][hh] : g_tkT[i][hh];
                float p       = isBot ? g_bvT[i][hh] : g_tvT[i][hh];
#pragma unroll
                for (int j = 0; j < NC; ++j) { cl[j] += p; p *= kv; }
            }
            float* dst = (isBot ? cLn : cLp) + hh * NCP;
#pragma unroll
            for (int j = 0; j < NC; ++j) dst[j] = cl[j] * c_invf[j];
        }
        __syncthreads();
    }

    if (t == 448) {
        float l = hg_b[0];
#pragma unroll
        for (int w = 0; w < 16; ++w) l += impred[w] * (1.f / (float)NN);
        const float imp = 1.f / (1.f + expf(-l));
        early_s = (imp < 0.1f) ? 1 : 0;
    }
    {   // gx (1/thread), from block-local gqS
        const int hh = t & 63;
        const float ag = gqS[t] * SCALE;
        gxS[t] = horner8(cSvS + hh * NCP, ag) / horner8(cDgS + hh * NCP, ag);
    }
    // local attention (1/thread)
    {
        const int hh = t & 63;
        const float a = qsS[t] * SCALE;
        const float D = horner8(cDs + hh * NCP, a);
        float num;
        if (a > 0.f)      num = horner8(cLp + hh * NCP, a);
        else if (a < 0.f) num = horner8(cLn + hh * NCP, a);
        else              num = g_vpreT[km - 1][hh];
        lxS[t] = num / D;
    }
    asm volatile("cp.async.wait_group 0;" ::: "memory");
    __syncthreads();

    // fuse: 256 threads x 2 rows (weights from smem)
    if (t < 256) {
        const int c = t & 63, rp = t >> 6;
        const int r0 = rp * 2, r1 = r0 + 1;
        const float4* lx4 = (const float4*)lxS;
        const float4* gx4 = (const float4*)gxS;
        float f0 = fus_b[c], f1 = f0;
#pragma unroll
        for (int j4 = 0; j4 < 16; ++j4) {
            const float w0 = fusW[(j4 * 4 + 0) * 64 + c];
            const float w1 = fusW[(j4 * 4 + 1) * 64 + c];
            const float w2 = fusW[(j4 * 4 + 2) * 64 + c];
            const float w3 = fusW[(j4 * 4 + 3) * 64 + c];
            const float4 a0 = lx4[r0 * 16 + j4];
            const float4 a1 = lx4[r1 * 16 + j4];
            f0 = fmaf(a0.x, w0, f0); f0 = fmaf(a0.y, w1, f0);
            f0 = fmaf(a0.z, w2, f0); f0 = fmaf(a0.w, w3, f0);
            f1 = fmaf(a1.x, w0, f1); f1 = fmaf(a1.y, w1, f1);
            f1 = fmaf(a1.z, w2, f1); f1 = fmaf(a1.w, w3, f1);
        }
#pragma unroll
        for (int j4 = 0; j4 < 16; ++j4) {
            const float w0 = fusW[(64 + j4 * 4 + 0) * 64 + c];
            const float w1 = fusW[(64 + j4 * 4 + 1) * 64 + c];
            const float w2 = fusW[(64 + j4 * 4 + 2) * 64 + c];
            const float w3 = fusW[(64 + j4 * 4 + 3) * 64 + c];
            const float4 a0 = gx4[r0 * 16 + j4];
            const float4 a1 = gx4[r1 * 16 + j4];
            f0 = fmaf(a0.x, w0, f0); f0 = fmaf(a0.y, w1, f0);
            f0 = fmaf(a0.z, w2, f0); f0 = fmaf(a0.w, w3, f0);
            f1 = fmaf(a1.x, w0, f1); f1 = fmaf(a1.y, w1, f1);
            f1 = fmaf(a1.z, w2, f1); f1 = fmaf(a1.w, w3, f1);
        }
        ttS[r0 * 64 + c] = xmS[r0 * 64 + c] + f0;
        ttS[r1 * 64 + c] = xmS[r1 * 64 + c] + f1;
    }
    __syncthreads();
    const int early = early_s;
    if (t < 256) {   // proj: 2 rows per thread (weights from smem)
        const int c = t & 63, rp = t >> 6;
        const int r0 = rp * 2, r1 = r0 + 1;
        const float4* tt4 = (const float4*)ttS;
        float o0 = proj_b[c], o1 = o0;
#pragma unroll
        for (int j4 = 0; j4 < 16; ++j4) {
            const float w0 = projW[(j4 * 4 + 0) * 64 + c];
            const float w1 = projW[(j4 * 4 + 1) * 64 + c];
            const float w2 = projW[(j4 * 4 + 2) * 64 + c];
            const float w3 = projW[(j4 * 4 + 3) * 64 + c];
            const float4 a0 = tt4[r0 * 16 + j4];
            const float4 a1 = tt4[r1 * 16 + j4];
            o0 = fmaf(a0.x, w0, o0); o0 = fmaf(a0.y, w1, o0);
            o0 = fmaf(a0.z, w2, o0); o0 = fmaf(a0.w, w3, o0);
            o1 = fmaf(a1.x, w0, o1); o1 = fmaf(a1.y, w1, o1);
            o1 = fmaf(a1.z, w2, o1); o1 = fmaf(a1.w, w3, o1);
        }
        out[(n0 + r0) * 64 + c] = early ? xs[r0 * 64 + c] : o0;
        out[(n0 + r1) * 64 + c] = early ? xs[r1 * 64 + c] : o1;
    }
}

extern "C" void kernel_launch(void* const* d_in, const int* in_sizes, int n_in,
                              void* d_out, int out_size) {
    const float* x      = (const float*)d_in[0];
    const float* qkv_w  = (const float*)d_in[1];
    const float* qkv_b  = (const float*)d_in[2];
    const float* gqkv_w = (const float*)d_in[3];
    const float* gqkv_b = (const float*)d_in[4];
    const float* cg_w   = (const float*)d_in[5];
    const float* cg_b   = (const float*)d_in[6];
    const float* hg_w   = (const float*)d_in[7];
    const float* hg_b   = (const float*)d_in[8];
    const float* fus_w  = (const float*)d_in[9];
    const float* fus_b  = (const float*)d_in[10];
    const float* proj_w = (const float*)d_in[11];
    const float* proj_b = (const float*)d_in[12];
    float* out = (float*)d_out;

    // opt-in for static+dynamic smem > 48KB (idempotent host call; not a
    // stream op, not an allocation -> graph-capture safe)
    cudaFuncSetAttribute(fused_kernel,
                         cudaFuncAttributeMaxDynamicSharedMemorySize, 49152);

    fused_kernel<<<NB, NT, 49152>>>(x, qkv_w, qkv_b, gqkv_w, gqkv_b, cg_w, cg_b,
                                    hg_w, hg_b, fus_w, fus_b, proj_w, proj_b, out);
}